// round 15
// baseline (speedup 1.0000x reference)
#include <cuda_runtime.h>
#include <cstdint>

// ---------------- problem dims ----------------
#define MDIM 8192
#define NDIM 2048
#define KDIM 2048
#define BM 128
#define BN 128
#define BK 64
#define NSTAGE 4
#define NCHUNK (KDIM / BK)   // 32

// smem: rows padded to 80 bytes (16B-aligned, conflict-free for ldmatrix)
#define ROWPAD 80
#define A_BYTES (BM * ROWPAD)            // 10240
#define B_BYTES (BN * ROWPAD)            // 10240
#define STAGE_BYTES (A_BYTES + B_BYTES)  // 20480
#define SMEM_TOTAL (NSTAGE * STAGE_BYTES) // 81920

#define NPART 1024
#define XBLOCKS 4096   // 2 rows per block
#define WBLOCKS 4096   // (2048*2048/4)/256

// ---------------- device scratch ----------------
static __device__ float g_partial[NPART];
static __device__ float g_scale;
static __device__ float g_gamma[MDIM];
static __device__ int8_t g_qw[(size_t)NDIM * KDIM];
static __device__ int8_t g_qx[(size_t)MDIM * KDIM];
static __device__ unsigned g_gate;   // wabs blocks completed
static __device__ unsigned g_done;   // wquant blocks completed

// ---------------- helpers ----------------
__device__ __forceinline__ uint32_t smem_u32(const void* p) {
    uint32_t a;
    asm("{ .reg .u64 t; cvta.to.shared.u64 t, %1; cvt.u32.u64 %0, t; }"
        : "=r"(a) : "l"(p));
    return a;
}

__device__ __forceinline__ void ldgsts16(uint32_t s, const void* g) {
    asm volatile("cp.async.cg.shared.global [%0], [%1], 16;" :: "r"(s), "l"(g));
}
#define CP_COMMIT() asm volatile("cp.async.commit_group;" ::: "memory")
#define CP_WAIT2()  asm volatile("cp.async.wait_group 2;" ::: "memory")

__device__ __forceinline__ void ldsm_x4(uint32_t* r, uint32_t addr) {
    asm volatile("ldmatrix.sync.aligned.m8n8.x4.shared.b16 {%0,%1,%2,%3}, [%4];"
                 : "=r"(r[0]), "=r"(r[1]), "=r"(r[2]), "=r"(r[3]) : "r"(addr));
}

__device__ __forceinline__ void mma_s8(int* c, const uint32_t* a,
                                       uint32_t b0, uint32_t b1) {
    asm volatile(
        "mma.sync.aligned.m16n8k32.row.col.s32.s8.s8.s32 "
        "{%0,%1,%2,%3}, {%4,%5,%6,%7}, {%8,%9}, {%0,%1,%2,%3};"
        : "+r"(c[0]), "+r"(c[1]), "+r"(c[2]), "+r"(c[3])
        : "r"(a[0]), "r"(a[1]), "r"(a[2]), "r"(a[3]), "r"(b0), "r"(b1));
}

__device__ __forceinline__ uint32_t pack_s8(int a, int b, int c, int d) {
    return (a & 0xFF) | ((b & 0xFF) << 8) | ((c & 0xFF) << 16) | ((d & 0xFF) << 24);
}

// ---------------- fused prepass kernel ----------------
// grid layout: [0, NPART)              : |w| partial sums (release g_gate)
//              [NPART, NPART+XBLOCKS)  : activation quant, 2 rows/block
//              [NPART+XBLOCKS, ...)    : weight quant (gated on g_gate)
#define WSTRIDE (NPART * 256)   // 262144 float4s
__global__ void k_prep(const float* __restrict__ x,
                       const float* __restrict__ w) {
    const int bid = blockIdx.x;
    const int tid = threadIdx.x;

    if (bid < NPART) {
        // ---- |w| partial sum path ----
        __shared__ float red[8];
        const int lane = tid & 31;
        const float4* wv = reinterpret_cast<const float4*>(w);
        const int base = bid * 256 + tid;
        float4 v0 = wv[base];
        float4 v1 = wv[base + WSTRIDE];
        float4 v2 = wv[base + 2 * WSTRIDE];
        float4 v3 = wv[base + 3 * WSTRIDE];
        float s0 = (fabsf(v0.x) + fabsf(v0.y)) + (fabsf(v0.z) + fabsf(v0.w));
        float s1 = (fabsf(v1.x) + fabsf(v1.y)) + (fabsf(v1.z) + fabsf(v1.w));
        float s2 = (fabsf(v2.x) + fabsf(v2.y)) + (fabsf(v2.z) + fabsf(v2.w));
        float s3 = (fabsf(v3.x) + fabsf(v3.y)) + (fabsf(v3.z) + fabsf(v3.w));
        float s = (s0 + s1) + (s2 + s3);
        for (int o = 16; o > 0; o >>= 1)
            s += __shfl_xor_sync(0xFFFFFFFFu, s, o);
        if (lane == 0) red[tid >> 5] = s;
        __syncthreads();
        if (tid == 0) {
            float t = ((red[0] + red[1]) + (red[2] + red[3])) +
                      ((red[4] + red[5]) + (red[6] + red[7]));
            g_partial[bid] = t;
            __threadfence();
            atomicAdd(&g_gate, 1u);
        }
    } else if (bid < NPART + XBLOCKS) {
        // ---- activation path: rows 2*(bid-NPART), +1 ----
        __shared__ float wmax[16];
        const int r0 = (bid - NPART) * 2;
        const float4* x0 = reinterpret_cast<const float4*>(x + (size_t)r0 * KDIM);
        const float4* x1 = reinterpret_cast<const float4*>(x + (size_t)(r0 + 1) * KDIM);
        float4 a0 = x0[tid];
        float4 a1 = x0[tid + 256];
        float4 b0 = x1[tid];
        float4 b1 = x1[tid + 256];
        float m0 = fmaxf(fmaxf(fabsf(a0.x), fabsf(a0.y)), fmaxf(fabsf(a0.z), fabsf(a0.w)));
        m0 = fmaxf(m0, fmaxf(fmaxf(fabsf(a1.x), fabsf(a1.y)), fmaxf(fabsf(a1.z), fabsf(a1.w))));
        float m1 = fmaxf(fmaxf(fabsf(b0.x), fabsf(b0.y)), fmaxf(fabsf(b0.z), fabsf(b0.w)));
        m1 = fmaxf(m1, fmaxf(fmaxf(fabsf(b1.x), fabsf(b1.y)), fmaxf(fabsf(b1.z), fabsf(b1.w))));
        for (int o = 16; o > 0; o >>= 1) {
            m0 = fmaxf(m0, __shfl_xor_sync(0xFFFFFFFFu, m0, o));
            m1 = fmaxf(m1, __shfl_xor_sync(0xFFFFFFFFu, m1, o));
        }
        if ((tid & 31) == 0) {
            wmax[(tid >> 5) * 2] = m0;
            wmax[(tid >> 5) * 2 + 1] = m1;
        }
        __syncthreads();
        if (tid == 0) {
            float t0 = wmax[0], t1 = wmax[1];
            for (int i = 1; i < 8; i++) {
                t0 = fmaxf(t0, wmax[i * 2]);
                t1 = fmaxf(t1, wmax[i * 2 + 1]);
            }
            t0 = fmaxf(t0, 1e-5f);
            t1 = fmaxf(t1, 1e-5f);
            wmax[0] = t0;
            wmax[1] = t1;
            g_gamma[r0] = t0;
            g_gamma[r0 + 1] = t1;
        }
        __syncthreads();
        const float rq0 = 128.0f / wmax[0];
        const float rq1 = 128.0f / wmax[1];
        uint32_t* q0 = reinterpret_cast<uint32_t*>(g_qx + (size_t)r0 * KDIM);
        uint32_t* q1 = reinterpret_cast<uint32_t*>(g_qx + (size_t)(r0 + 1) * KDIM);
#define QV(v, rq) min(127, max(-128, __float2int_rn((v) * (rq))))
        q0[tid]       = pack_s8(QV(a0.x, rq0), QV(a0.y, rq0), QV(a0.z, rq0), QV(a0.w, rq0));
        q0[tid + 256] = pack_s8(QV(a1.x, rq0), QV(a1.y, rq0), QV(a1.z, rq0), QV(a1.w, rq0));
        q1[tid]       = pack_s8(QV(b0.x, rq1), QV(b0.y, rq1), QV(b0.z, rq1), QV(b0.w, rq1));
        q1[tid + 256] = pack_s8(QV(b1.x, rq1), QV(b1.y, rq1), QV(b1.z, rq1), QV(b1.w, rq1));
#undef QV
    } else {
        // ---- weight quant path (gated on wabs completion) ----
        const int wi = bid - NPART - XBLOCKS;
        __shared__ float sred[8];
        __shared__ float s_scale;
        if (tid == 0) {
            while (atomicAdd(&g_gate, 0u) < (unsigned)NPART) __nanosleep(64);
        }
        __syncthreads();
        __threadfence();   // acquire: partials visible
        float s = ((g_partial[tid] + g_partial[tid + 256]) +
                   (g_partial[tid + 512] + g_partial[tid + 768]));
        for (int o = 16; o > 0; o >>= 1)
            s += __shfl_xor_sync(0xFFFFFFFFu, s, o);
        if ((tid & 31) == 0) sred[tid >> 5] = s;
        __syncthreads();
        if (tid == 0) {
            float t = ((sred[0] + sred[1]) + (sred[2] + sred[3])) +
                      ((sred[4] + sred[5]) + (sred[6] + sred[7]));
            t = fmaxf(t / (float)(NDIM * KDIM), 1e-5f);
            s_scale = t;
            if (wi == 0) g_scale = t;
        }
        __syncthreads();
        const float inv = 1.0f / s_scale;
        const int i = wi * 256 + tid;   // float4 index
        float4 v = reinterpret_cast<const float4*>(w)[i];
        int q0 = min(1, max(-1, __float2int_rn(v.x * inv)));
        int q1 = min(1, max(-1, __float2int_rn(v.y * inv)));
        int q2 = min(1, max(-1, __float2int_rn(v.z * inv)));
        int q3 = min(1, max(-1, __float2int_rn(v.w * inv)));
        reinterpret_cast<uint32_t*>(g_qw)[i] = pack_s8(q0, q1, q2, q3);
        // replay hygiene: last w-block resets counters (all gates already passed)
        __threadfence();
        if (tid == 0) {
            unsigned prev = atomicAdd(&g_done, 1u);
            if (prev == (unsigned)(WBLOCKS - 1)) {
                atomicExch(&g_gate, 0u);
                atomicExch(&g_done, 0u);
            }
        }
    }
}

// ---------------- GEMM (R4 config, measured at legacy-IMMA floor) ----------------

__device__ __forceinline__ void load_stage(uint32_t sb, int stage, int kc,
                                           const int8_t* gA, const int8_t* gB,
                                           int tid) {
    uint32_t sA = sb + stage * STAGE_BYTES;
    const int8_t* pA = gA + kc * BK;
#pragma unroll
    for (int i = 0; i < 2; i++) {          // 128 rows x 4 segs = 512
        int u = tid + 256 * i;
        int row = u >> 2, seg = u & 3;
        ldgsts16(sA + row * ROWPAD + seg * 16, pA + (size_t)row * KDIM + seg * 16);
    }
    uint32_t sB = sA + A_BYTES;
    const int8_t* pB = gB + kc * BK;
#pragma unroll
    for (int i = 0; i < 2; i++) {
        int u = tid + 256 * i;
        int row = u >> 2, seg = u & 3;
        ldgsts16(sB + row * ROWPAD + seg * 16, pB + (size_t)row * KDIM + seg * 16);
    }
}

__global__ void __launch_bounds__(256, 1)
gemm_kernel(const float* __restrict__ bias, float* __restrict__ out) {
    extern __shared__ char smem[];
    const uint32_t sb = smem_u32(smem);
    const int tid = threadIdx.x;
    const int lane = tid & 31, wid = tid >> 5;
    const int warp_m = wid >> 2;       // 0..1 -> 64 rows each
    const int warp_n = wid & 3;        // 0..3 -> 32 cols each
    const int m0 = blockIdx.y * BM;
    const int n0 = blockIdx.x * BN;
    const int8_t* gA = g_qx + (size_t)m0 * KDIM;
    const int8_t* gB = g_qw + (size_t)n0 * KDIM;

    int acc[4][4][4];
#pragma unroll
    for (int i = 0; i < 4; i++)
#pragma unroll
        for (int j = 0; j < 4; j++)
#pragma unroll
            for (int k = 0; k < 4; k++) acc[i][j][k] = 0;

    // prologue: 3 stages in flight
#pragma unroll
    for (int s = 0; s < NSTAGE - 1; s++) {
        load_stage(sb, s, s, gA, gB, tid);
        CP_COMMIT();
    }

    const int row_lo = lane & 15;
    const int col16 = lane >> 4;

    for (int kc = 0; kc < NCHUNK; kc++) {
        CP_WAIT2();
        __syncthreads();
        const int pk = kc + NSTAGE - 1;
        if (pk < NCHUNK) load_stage(sb, pk & (NSTAGE - 1), pk, gA, gB, tid);
        CP_COMMIT();

        const int st = kc & (NSTAGE - 1);
        const uint32_t sA = sb + st * STAGE_BYTES;
        const uint32_t sB = sA + A_BYTES;
#pragma unroll
        for (int ks = 0; ks < 2; ks++) {
            const uint32_t koff = ks * 32 + col16 * 16;
            uint32_t afr[4][4];
#pragma unroll
            for (int fm = 0; fm < 4; fm++)
                ldsm_x4(afr[fm],
                        sA + (warp_m * 64 + fm * 16 + row_lo) * ROWPAD + koff);
            uint32_t bfr[2][4];
#pragma unroll
            for (int pr = 0; pr < 2; pr++)
                ldsm_x4(bfr[pr],
                        sB + (warp_n * 32 + pr * 16 + row_lo) * ROWPAD + koff);
#pragma unroll
            for (int fm = 0; fm < 4; fm++)
#pragma unroll
                for (int fn = 0; fn < 4; fn++) {
                    const int pr = fn >> 1, od = fn & 1;
                    mma_s8(acc[fm][fn], afr[fm], bfr[pr][od], bfr[pr][2 + od]);
                }
        }
    }

    // epilogue: out[r][c] = (acc + bias[c]) * scale * gamma[r] / 128
    const float sc = g_scale * (1.0f / 128.0f);
#pragma unroll
    for (int fm = 0; fm < 4; fm++) {
        const int r = m0 + warp_m * 64 + fm * 16 + (lane >> 2);
        const float cf0 = sc * g_gamma[r];
        const float cf1 = sc * g_gamma[r + 8];
#pragma unroll
        for (int fn = 0; fn < 4; fn++) {
            const int c = n0 + warp_n * 32 + fn * 8 + (lane & 3) * 2;
            const float b0 = bias[c], b1 = bias[c + 1];
            float2 v0, v1;
            v0.x = ((float)acc[fm][fn][0] + b0) * cf0;
            v0.y = ((float)acc[fm][fn][1] + b1) * cf0;
            v1.x = ((float)acc[fm][fn][2] + b0) * cf1;
            v1.y = ((float)acc[fm][fn][3] + b1) * cf1;
            *reinterpret_cast<float2*>(&out[(size_t)r * NDIM + c]) = v0;
            *reinterpret_cast<float2*>(&out[(size_t)(r + 8) * NDIM + c]) = v1;
        }
    }
}

// ---------------- launch ----------------
extern "C" void kernel_launch(void* const* d_in, const int* in_sizes, int n_in,
                              void* d_out, int out_size) {
    const float* x = (const float*)d_in[0];
    const float* w = (const float*)d_in[1];
    const float* bias = (const float*)d_in[2];
    float* out = (float*)d_out;

    cudaFuncSetAttribute(gemm_kernel, cudaFuncAttributeMaxDynamicSharedMemorySize,
                         SMEM_TOTAL);

    k_prep<<<NPART + XBLOCKS + WBLOCKS, 256>>>(x, w);

    dim3 grid(NDIM / BN, MDIM / BM);
    gemm_kernel<<<grid, 256, SMEM_TOTAL>>>(bias, out);
}

// round 17
// speedup vs baseline: 1.1135x; 1.1135x over previous
#include <cuda_runtime.h>
#include <cstdint>

// ---------------- problem dims ----------------
#define MDIM 8192
#define NDIM 2048
#define KDIM 2048
#define BM 128
#define BN 128
#define BK 64
#define NSTAGE 4
#define NCHUNK (KDIM / BK)   // 32

// smem: rows padded to 80 bytes (16B-aligned, conflict-free for ldmatrix)
#define ROWPAD 80
#define A_BYTES (BM * ROWPAD)            // 10240
#define B_BYTES (BN * ROWPAD)            // 10240
#define STAGE_BYTES (A_BYTES + B_BYTES)  // 20480
#define SMEM_TOTAL (NSTAGE * STAGE_BYTES) // 81920

#define NPART 1024
#define XBLOCKS 4096   // 2 rows per block
#define WBLOCKS 4096   // (2048*2048/4)/256

// ---------------- device scratch ----------------
static __device__ float g_partial[NPART];
static __device__ float g_scale;
static __device__ float g_gamma[MDIM];
static __device__ int8_t g_qw[(size_t)NDIM * KDIM];
static __device__ int8_t g_qx[(size_t)MDIM * KDIM];

// ---------------- helpers ----------------
__device__ __forceinline__ uint32_t smem_u32(const void* p) {
    uint32_t a;
    asm("{ .reg .u64 t; cvta.to.shared.u64 t, %1; cvt.u32.u64 %0, t; }"
        : "=r"(a) : "l"(p));
    return a;
}

__device__ __forceinline__ void ldgsts16(uint32_t s, const void* g) {
    asm volatile("cp.async.cg.shared.global [%0], [%1], 16;" :: "r"(s), "l"(g));
}
#define CP_COMMIT() asm volatile("cp.async.commit_group;" ::: "memory")
#define CP_WAIT2()  asm volatile("cp.async.wait_group 2;" ::: "memory")

__device__ __forceinline__ void ldsm_x4(uint32_t* r, uint32_t addr) {
    asm volatile("ldmatrix.sync.aligned.m8n8.x4.shared.b16 {%0,%1,%2,%3}, [%4];"
                 : "=r"(r[0]), "=r"(r[1]), "=r"(r[2]), "=r"(r[3]) : "r"(addr));
}

__device__ __forceinline__ void mma_s8(int* c, const uint32_t* a,
                                       uint32_t b0, uint32_t b1) {
    asm volatile(
        "mma.sync.aligned.m16n8k32.row.col.s32.s8.s8.s32 "
        "{%0,%1,%2,%3}, {%4,%5,%6,%7}, {%8,%9}, {%0,%1,%2,%3};"
        : "+r"(c[0]), "+r"(c[1]), "+r"(c[2]), "+r"(c[3])
        : "r"(a[0]), "r"(a[1]), "r"(a[2]), "r"(a[3]), "r"(b0), "r"(b1));
}

__device__ __forceinline__ uint32_t pack_s8(int a, int b, int c, int d) {
    return (a & 0xFF) | ((b & 0xFF) << 8) | ((c & 0xFF) << 16) | ((d & 0xFF) << 24);
}

// ---------------- prepass kernel 1: |w| partial sums ----------------
#define WSTRIDE (NPART * 256)   // 262144 float4s
__global__ void k_wabs(const float* __restrict__ w) {
    __shared__ float red[8];
    const int tid = threadIdx.x;
    const int lane = tid & 31;
    const float4* wv = reinterpret_cast<const float4*>(w);
    const int base = blockIdx.x * 256 + tid;
    float4 v0 = wv[base];
    float4 v1 = wv[base + WSTRIDE];
    float4 v2 = wv[base + 2 * WSTRIDE];
    float4 v3 = wv[base + 3 * WSTRIDE];
    float s0 = (fabsf(v0.x) + fabsf(v0.y)) + (fabsf(v0.z) + fabsf(v0.w));
    float s1 = (fabsf(v1.x) + fabsf(v1.y)) + (fabsf(v1.z) + fabsf(v1.w));
    float s2 = (fabsf(v2.x) + fabsf(v2.y)) + (fabsf(v2.z) + fabsf(v2.w));
    float s3 = (fabsf(v3.x) + fabsf(v3.y)) + (fabsf(v3.z) + fabsf(v3.w));
    float s = (s0 + s1) + (s2 + s3);
    for (int o = 16; o > 0; o >>= 1)
        s += __shfl_xor_sync(0xFFFFFFFFu, s, o);
    if (lane == 0) red[tid >> 5] = s;
    __syncthreads();
    if (tid == 0) {
        float t = ((red[0] + red[1]) + (red[2] + red[3])) +
                  ((red[4] + red[5]) + (red[6] + red[7]));
        g_partial[blockIdx.x] = t;
    }
}

// ---------------- prepass kernel 2: fused quantization ----------------
__global__ void k_fused_quant(const float* __restrict__ x,
                              const float* __restrict__ w) {
    const int bid = blockIdx.x;
    const int tid = threadIdx.x;

    if (bid < XBLOCKS) {
        // ---- activation path: rows 2*bid, 2*bid+1 ----
        __shared__ float wmax[16];
        const int r0 = bid * 2;
        const float4* x0 = reinterpret_cast<const float4*>(x + (size_t)r0 * KDIM);
        const float4* x1 = reinterpret_cast<const float4*>(x + (size_t)(r0 + 1) * KDIM);
        float4 a0 = x0[tid];
        float4 a1 = x0[tid + 256];
        float4 b0 = x1[tid];
        float4 b1 = x1[tid + 256];
        float m0 = fmaxf(fmaxf(fabsf(a0.x), fabsf(a0.y)), fmaxf(fabsf(a0.z), fabsf(a0.w)));
        m0 = fmaxf(m0, fmaxf(fmaxf(fabsf(a1.x), fabsf(a1.y)), fmaxf(fabsf(a1.z), fabsf(a1.w))));
        float m1 = fmaxf(fmaxf(fabsf(b0.x), fabsf(b0.y)), fmaxf(fabsf(b0.z), fabsf(b0.w)));
        m1 = fmaxf(m1, fmaxf(fmaxf(fabsf(b1.x), fabsf(b1.y)), fmaxf(fabsf(b1.z), fabsf(b1.w))));
        for (int o = 16; o > 0; o >>= 1) {
            m0 = fmaxf(m0, __shfl_xor_sync(0xFFFFFFFFu, m0, o));
            m1 = fmaxf(m1, __shfl_xor_sync(0xFFFFFFFFu, m1, o));
        }
        if ((tid & 31) == 0) {
            wmax[(tid >> 5) * 2] = m0;
            wmax[(tid >> 5) * 2 + 1] = m1;
        }
        __syncthreads();
        if (tid == 0) {
            float t0 = wmax[0], t1 = wmax[1];
            for (int i = 1; i < 8; i++) {
                t0 = fmaxf(t0, wmax[i * 2]);
                t1 = fmaxf(t1, wmax[i * 2 + 1]);
            }
            t0 = fmaxf(t0, 1e-5f);
            t1 = fmaxf(t1, 1e-5f);
            wmax[0] = t0;
            wmax[1] = t1;
            g_gamma[r0] = t0;
            g_gamma[r0 + 1] = t1;
        }
        __syncthreads();
        const float rq0 = 128.0f / wmax[0];
        const float rq1 = 128.0f / wmax[1];
        uint32_t* q0 = reinterpret_cast<uint32_t*>(g_qx + (size_t)r0 * KDIM);
        uint32_t* q1 = reinterpret_cast<uint32_t*>(g_qx + (size_t)(r0 + 1) * KDIM);
#define QV(v, rq) min(127, max(-128, __float2int_rn((v) * (rq))))
        q0[tid]       = pack_s8(QV(a0.x, rq0), QV(a0.y, rq0), QV(a0.z, rq0), QV(a0.w, rq0));
        q0[tid + 256] = pack_s8(QV(a1.x, rq0), QV(a1.y, rq0), QV(a1.z, rq0), QV(a1.w, rq0));
        q1[tid]       = pack_s8(QV(b0.x, rq1), QV(b0.y, rq1), QV(b0.z, rq1), QV(b0.w, rq1));
        q1[tid + 256] = pack_s8(QV(b1.x, rq1), QV(b1.y, rq1), QV(b1.z, rq1), QV(b1.w, rq1));
#undef QV
    } else {
        // ---- weight path: reduce 1024 partials (deterministic, identical per block) ----
        __shared__ float sred[8];
        __shared__ float s_scale;
        float s = ((g_partial[tid] + g_partial[tid + 256]) +
                   (g_partial[tid + 512] + g_partial[tid + 768]));
        for (int o = 16; o > 0; o >>= 1)
            s += __shfl_xor_sync(0xFFFFFFFFu, s, o);
        if ((tid & 31) == 0) sred[tid >> 5] = s;
        __syncthreads();
        if (tid == 0) {
            float t = ((sred[0] + sred[1]) + (sred[2] + sred[3])) +
                      ((sred[4] + sred[5]) + (sred[6] + sred[7]));
            t = fmaxf(t / (float)(NDIM * KDIM), 1e-5f);
            s_scale = t;
            if (bid == XBLOCKS) g_scale = t;
        }
        __syncthreads();
        const float inv = 1.0f / s_scale;
        const int i = (bid - XBLOCKS) * 256 + tid;   // float4 index
        float4 v = reinterpret_cast<const float4*>(w)[i];
        int q0 = min(1, max(-1, __float2int_rn(v.x * inv)));
        int q1 = min(1, max(-1, __float2int_rn(v.y * inv)));
        int q2 = min(1, max(-1, __float2int_rn(v.z * inv)));
        int q3 = min(1, max(-1, __float2int_rn(v.w * inv)));
        reinterpret_cast<uint32_t*>(g_qw)[i] = pack_s8(q0, q1, q2, q3);
    }
}

// ---------------- GEMM ----------------

__device__ __forceinline__ void load_stage(uint32_t sb, int stage, int kc,
                                           const int8_t* gA, const int8_t* gB,
                                           int tid) {
    uint32_t sA = sb + stage * STAGE_BYTES;
    const int8_t* pA = gA + kc * BK;
#pragma unroll
    for (int i = 0; i < 2; i++) {          // 128 rows x 4 segs = 512
        int u = tid + 256 * i;
        int row = u >> 2, seg = u & 3;
        ldgsts16(sA + row * ROWPAD + seg * 16, pA + (size_t)row * KDIM + seg * 16);
    }
    uint32_t sB = sA + A_BYTES;
    const int8_t* pB = gB + kc * BK;
#pragma unroll
    for (int i = 0; i < 2; i++) {
        int u = tid + 256 * i;
        int row = u >> 2, seg = u & 3;
        ldgsts16(sB + row * ROWPAD + seg * 16, pB + (size_t)row * KDIM + seg * 16);
    }
}

__global__ void __launch_bounds__(256, 1)
gemm_kernel(const float* __restrict__ bias, float* __restrict__ out) {
    extern __shared__ char smem[];
    const uint32_t sb = smem_u32(smem);
    const int tid = threadIdx.x;
    const int lane = tid & 31, wid = tid >> 5;
    const int warp_m = wid >> 2;       // 0..1 -> 64 rows each
    const int warp_n = wid & 3;        // 0..3 -> 32 cols each
    const int m0 = blockIdx.y * BM;
    const int n0 = blockIdx.x * BN;
    const int8_t* gA = g_qx + (size_t)m0 * KDIM;
    const int8_t* gB = g_qw + (size_t)n0 * KDIM;

    int acc[4][4][4];
#pragma unroll
    for (int i = 0; i < 4; i++)
#pragma unroll
        for (int j = 0; j < 4; j++)
#pragma unroll
            for (int k = 0; k < 4; k++) acc[i][j][k] = 0;

    // prologue: 3 stages in flight
#pragma unroll
    for (int s = 0; s < NSTAGE - 1; s++) {
        load_stage(sb, s, s, gA, gB, tid);
        CP_COMMIT();
    }

    const int row_lo = lane & 15;
    const int col16 = lane >> 4;

    for (int kc = 0; kc < NCHUNK; kc++) {
        CP_WAIT2();
        __syncthreads();

        const int st = kc & (NSTAGE - 1);
        const uint32_t sA = sb + st * STAGE_BYTES;
        const uint32_t sB = sA + A_BYTES;

        // 1) front-load ALL fragments for both ks-steps (12 LDSMs in flight)
        uint32_t afr[2][4][4];
        uint32_t bfr[2][2][4];
#pragma unroll
        for (int ks = 0; ks < 2; ks++) {
            const uint32_t koff = ks * 32 + col16 * 16;
#pragma unroll
            for (int fm = 0; fm < 4; fm++)
                ldsm_x4(afr[ks][fm],
                        sA + (warp_m * 64 + fm * 16 + row_lo) * ROWPAD + koff);
#pragma unroll
            for (int pr = 0; pr < 2; pr++)
                ldsm_x4(bfr[ks][pr],
                        sB + (warp_n * 32 + pr * 16 + row_lo) * ROWPAD + koff);
        }

        // 2) prefetch next chunk (LSU issue overlaps MMA burst below)
        const int pk = kc + NSTAGE - 1;
        if (pk < NCHUNK) load_stage(sb, pk & (NSTAGE - 1), pk, gA, gB, tid);
        CP_COMMIT();

        // 3) 64-MMA burst, limited only by tensor-pipe rate
#pragma unroll
        for (int ks = 0; ks < 2; ks++)
#pragma unroll
            for (int fm = 0; fm < 4; fm++)
#pragma unroll
                for (int fn = 0; fn < 4; fn++) {
                    const int pr = fn >> 1, od = fn & 1;
                    mma_s8(acc[fm][fn], afr[ks][fm],
                           bfr[ks][pr][od], bfr[ks][pr][2 + od]);
                }
    }

    // epilogue: out[r][c] = (acc + bias[c]) * scale * gamma[r] / 128
    const float sc = g_scale * (1.0f / 128.0f);
#pragma unroll
    for (int fm = 0; fm < 4; fm++) {
        const int r = m0 + warp_m * 64 + fm * 16 + (lane >> 2);
        const float cf0 = sc * g_gamma[r];
        const float cf1 = sc * g_gamma[r + 8];
#pragma unroll
        for (int fn = 0; fn < 4; fn++) {
            const int c = n0 + warp_n * 32 + fn * 8 + (lane & 3) * 2;
            const float b0 = bias[c], b1 = bias[c + 1];
            float2 v0, v1;
            v0.x = ((float)acc[fm][fn][0] + b0) * cf0;
            v0.y = ((float)acc[fm][fn][1] + b1) * cf0;
            v1.x = ((float)acc[fm][fn][2] + b0) * cf1;
            v1.y = ((float)acc[fm][fn][3] + b1) * cf1;
            *reinterpret_cast<float2*>(&out[(size_t)r * NDIM + c]) = v0;
            *reinterpret_cast<float2*>(&out[(size_t)(r + 8) * NDIM + c]) = v1;
        }
    }
}

// ---------------- launch ----------------
extern "C" void kernel_launch(void* const* d_in, const int* in_sizes, int n_in,
                              void* d_out, int out_size) {
    const float* x = (const float*)d_in[0];
    const float* w = (const float*)d_in[1];
    const float* bias = (const float*)d_in[2];
    float* out = (float*)d_out;

    cudaFuncSetAttribute(gemm_kernel, cudaFuncAttributeMaxDynamicSharedMemorySize,
                         SMEM_TOTAL);

    k_wabs<<<NPART, 256>>>(w);
    k_fused_quant<<<XBLOCKS + WBLOCKS, 256>>>(x, w);

    dim3 grid(NDIM / BN, MDIM / BM);
    gemm_kernel<<<grid, 256, SMEM_TOTAL>>>(bias, out);
}